// round 5
// baseline (speedup 1.0000x reference)
#include <cuda_runtime.h>

typedef unsigned long long u64;

#define BB   64
#define TIN  1024
#define T1   1020
#define T2   1016
#define HH   12
#define LL   120
#define GG   48
#define RING 64
#define RM   (RING-1)
#define BH   (BB*HH)     /* 768 */
#define OUTSZ (BB*LL*HH) /* 92160 */
#define NW   8           /* warps per layer CTA */

// ---------------- device scratch (static, no allocation) ----------------
__device__ float g_y1[BB*6*T1];
__device__ float g_y2[BB*6*T2];
__device__ float g_part1[BB*12];
__device__ float g_part2[BB*12];
__device__ float g_feat[T2*BH];
__device__ float g_ring[(LL-1)*RING*BH];
__device__ float g_hlast[LL*BH];
__device__ int   g_progress[LL*NW];

// ---------------- helpers ----------------
__device__ __forceinline__ int ld_acq(const int* p){
  int v; asm volatile("ld.acquire.gpu.b32 %0, [%1];" : "=r"(v) : "l"(p)); return v;
}
__device__ __forceinline__ void st_rel(int* p, int v){
  asm volatile("st.release.gpu.b32 [%0], %1;" :: "l"(p), "r"(v));
}
__device__ __forceinline__ u64 pk2(float lo, float hi){
  u64 r; asm("mov.b64 %0, {%1, %2};" : "=l"(r) : "f"(lo), "f"(hi)); return r;
}
__device__ __forceinline__ void upk2(u64 v, float& lo, float& hi){
  asm("mov.b64 {%0, %1}, %2;" : "=f"(lo), "=f"(hi) : "l"(v));
}
__device__ __forceinline__ void ffma2(u64& acc, u64 a, u64 b){
  asm("fma.rn.f32x2 %0, %1, %2, %0;" : "+l"(acc) : "l"(a), "l"(b));
}
__device__ __forceinline__ float sigf(float x){
  float e = __expf(-x); return __fdividef(1.f, 1.f + e);
}
__device__ __forceinline__ float tanh_(float x){
  float ax = fabsf(x);
  float e  = __expf(-2.f*ax);
  float t  = __fdividef(1.f - e, 1.f + e);
  return (x < 0.f) ? -t : t;
}

// ---------------- init (reset pipeline flags each replay) ----------------
__global__ void k_init(){
  int i = blockIdx.x*blockDim.x + threadIdx.x;
  if (i < LL*NW) g_progress[i] = 0;
}

// ---------------- conv1 + batch-stat partials ----------------
__global__ void k_conv1(const float* __restrict__ x, const float* __restrict__ w,
                        const float* __restrict__ bias){
  __shared__ float xs[6*TIN];
  __shared__ float ws[180];
  __shared__ float bs[6];
  __shared__ float red[12][8];
  int b = blockIdx.x, tid = threadIdx.x;
  for (int i = tid; i < 6*TIN; i += 256) xs[i] = x[b*6*TIN + i];
  for (int i = tid; i < 180;   i += 256) ws[i] = w[i];
  if (tid < 6) bs[tid] = bias[tid];
  __syncthreads();
  float s[6] = {0,0,0,0,0,0}, q[6] = {0,0,0,0,0,0};
  for (int t = tid; t < T1; t += 256){
    float acc[6];
    #pragma unroll
    for (int co = 0; co < 6; co++) acc[co] = bs[co];
    #pragma unroll
    for (int ci = 0; ci < 6; ci++){
      float xr[5];
      #pragma unroll
      for (int k = 0; k < 5; k++) xr[k] = xs[ci*TIN + t + k];
      #pragma unroll
      for (int co = 0; co < 6; co++){
        const float* wp = &ws[co*30 + ci*5];
        #pragma unroll
        for (int k = 0; k < 5; k++) acc[co] += xr[k]*wp[k];
      }
    }
    #pragma unroll
    for (int co = 0; co < 6; co++){
      g_y1[b*6*T1 + co*T1 + t] = acc[co];
      s[co] += acc[co]; q[co] += acc[co]*acc[co];
    }
  }
  int lane = tid & 31, wrp = tid >> 5;
  #pragma unroll
  for (int c = 0; c < 6; c++){
    float v = s[c], u = q[c];
    #pragma unroll
    for (int o = 16; o; o >>= 1){
      v += __shfl_down_sync(0xffffffffu, v, o);
      u += __shfl_down_sync(0xffffffffu, u, o);
    }
    if (lane == 0){ red[c][wrp] = v; red[6+c][wrp] = u; }
  }
  __syncthreads();
  if (tid < 12){
    float a = 0.f;
    #pragma unroll
    for (int w8 = 0; w8 < 8; w8++) a += red[tid][w8];
    g_part1[b*12 + tid] = a;
  }
}

// ---------------- bn1+relu -> conv2 + stat partials ----------------
__global__ void k_conv2(const float* __restrict__ w, const float* __restrict__ bias,
                        const float* __restrict__ gamma, const float* __restrict__ beta){
  __shared__ float xs[6*T1];
  __shared__ float ws[180];
  __shared__ float bs[6];
  __shared__ float stt[12];
  __shared__ float sc[6], sh[6];
  __shared__ float red[12][8];
  int b = blockIdx.x, tid = threadIdx.x;
  if (tid < 12){
    float a = 0.f;
    for (int bb = 0; bb < BB; bb++) a += g_part1[bb*12 + tid];
    stt[tid] = a;
  }
  for (int i = tid; i < 180; i += 256) ws[i] = w[i];
  if (tid < 6) bs[tid] = bias[tid];
  __syncthreads();
  if (tid < 6){
    float inv  = 1.f / (64.f * 1020.f);
    float mean = stt[tid]*inv;
    float var  = stt[6+tid]*inv - mean*mean;
    float scl  = gamma[tid]*rsqrtf(var + 1e-5f);
    sc[tid] = scl; sh[tid] = beta[tid] - mean*scl;
  }
  __syncthreads();
  for (int i = tid; i < 6*T1; i += 256){
    int c = i / T1;
    float v = g_y1[b*6*T1 + i]*sc[c] + sh[c];
    xs[i] = fmaxf(v, 0.f);
  }
  __syncthreads();
  float s[6] = {0,0,0,0,0,0}, q[6] = {0,0,0,0,0,0};
  for (int t = tid; t < T2; t += 256){
    float acc[6];
    #pragma unroll
    for (int co = 0; co < 6; co++) acc[co] = bs[co];
    #pragma unroll
    for (int ci = 0; ci < 6; ci++){
      float xr[5];
      #pragma unroll
      for (int k = 0; k < 5; k++) xr[k] = xs[ci*T1 + t + k];
      #pragma unroll
      for (int co = 0; co < 6; co++){
        const float* wp = &ws[co*30 + ci*5];
        #pragma unroll
        for (int k = 0; k < 5; k++) acc[co] += xr[k]*wp[k];
      }
    }
    #pragma unroll
    for (int co = 0; co < 6; co++){
      g_y2[b*6*T2 + co*T2 + t] = acc[co];
      s[co] += acc[co]; q[co] += acc[co]*acc[co];
    }
  }
  int lane = tid & 31, wrp = tid >> 5;
  #pragma unroll
  for (int c = 0; c < 6; c++){
    float v = s[c], u = q[c];
    #pragma unroll
    for (int o = 16; o; o >>= 1){
      v += __shfl_down_sync(0xffffffffu, v, o);
      u += __shfl_down_sync(0xffffffffu, u, o);
    }
    if (lane == 0){ red[c][wrp] = v; red[6+c][wrp] = u; }
  }
  __syncthreads();
  if (tid < 12){
    float a = 0.f;
    #pragma unroll
    for (int w8 = 0; w8 < 8; w8++) a += red[tid][w8];
    g_part2[b*12 + tid] = a;
  }
}

// ---------------- bn2+relu -> attn projection -> feat[t][b][h] ----------------
__global__ void k_attn(const float* __restrict__ gamma, const float* __restrict__ beta,
                       const float* __restrict__ aw, const float* __restrict__ ab){
  __shared__ float xs[6*T2];
  __shared__ float stt[12];
  __shared__ float sc[6], sh[6];
  __shared__ float aws[72];
  __shared__ float abv[12];
  int b = blockIdx.x, tid = threadIdx.x;
  if (tid < 12){
    float a = 0.f;
    for (int bb = 0; bb < BB; bb++) a += g_part2[bb*12 + tid];
    stt[tid] = a;
  }
  if (tid < 72) aws[tid] = aw[tid];
  if (tid < 12) abv[tid] = ab[tid];
  __syncthreads();
  if (tid < 6){
    float inv  = 1.f / (64.f * 1016.f);
    float mean = stt[tid]*inv;
    float var  = stt[6+tid]*inv - mean*mean;
    float scl  = gamma[tid]*rsqrtf(var + 1e-5f);
    sc[tid] = scl; sh[tid] = beta[tid] - mean*scl;
  }
  __syncthreads();
  for (int i = tid; i < 6*T2; i += 256){
    int c = i / T2;
    float v = g_y2[b*6*T2 + i]*sc[c] + sh[c];
    xs[i] = fmaxf(v, 0.f);
  }
  __syncthreads();
  for (int i = tid; i < T2*HH; i += 256){
    int t = i / HH, h = i % HH;
    float acc = abv[h];
    #pragma unroll
    for (int c = 0; c < 6; c++) acc += xs[c*T2 + t]*aws[h*6 + c];
    g_feat[t*BH + b*12 + h] = fmaxf(acc, 0.f);
  }
}

// ---------------- pipelined 120-layer LSTM, warp-granular ----------------
// 1 layer per CTA. Lane-group of 4 owns one batch element (b = tid>>2,
// q = tid&3, cells 3q..3q+2); h exchanged via shfl. Warp w syncs only with
// warp w of neighbor layers via per-warp release/acquire flags.
// KEY (this round): on starvation, rebuild a 2-step cushion (spin to t+3)
// so the depth-1 input prefetch deterministically succeeds -> no exposed
// L2 latency inside the steady-state loop.
__global__ void __launch_bounds__(256,1) k_lstm(const float* __restrict__ wih,
                                                const float* __restrict__ whh,
                                                const float* __restrict__ bih,
                                                const float* __restrict__ bhh){
  int l = blockIdx.x, tid = threadIdx.x;
  int lane = tid & 31;
  int wz   = tid >> 5;          // warp id 0..7
  int q    = lane & 3;          // quarter within batch group
  int b    = tid >> 2;          // batch element 0..63

  __shared__ __align__(16) u64 wpk[GG][12];  // packed {w_k,w_{k+1}} per gate row over [x;h]

  const float* wi = wih + l*576;
  const float* wh = whh + l*576;
  for (int i = tid; i < GG*12; i += 256){
    int gg = i / 12, kp = i % 12;
    float w0, w1;
    if (kp < 6){ w0 = wi[gg*12 + 2*kp];      w1 = wi[gg*12 + 2*kp + 1];  }
    else       { w0 = wh[gg*12 + 2*kp - 12]; w1 = wh[gg*12 + 2*kp - 11]; }
    wpk[gg][kp] = pk2(w0, w1);
  }
  __syncthreads();

  // biases for this thread's 12 gate rows (row = gate*12 + 3q + j)
  float br[12];
  #pragma unroll
  for (int j = 0; j < 3; j++){
    #pragma unroll
    for (int g4 = 0; g4 < 4; g4++){
      int row = g4*12 + 3*q + j;
      br[j*4+g4] = bih[l*GG + row] + bhh[l*GG + row];
    }
  }

  float c0 = 0.f, c1 = 0.f, c2 = 0.f;
  float hl0 = 0.f, hl1 = 0.f, hl2 = 0.f;
  float*       ringo = (l < LL-1) ? (g_ring + (size_t)l*(RING*BH)) : (float*)0;
  const float* ringi = (l > 0)    ? (g_ring + (size_t)(l-1)*(RING*BH)) : (const float*)0;
  const int* flag_in  = (l > 0)    ? &g_progress[(l-1)*NW + wz] : (const int*)0;
  const int* flag_out = (l < LL-1) ? &g_progress[(l+1)*NW + wz] : (const int*)0;
  int* flag_me = &g_progress[l*NW + wz];

  int last_in = 0, last_out = 0;
  int have = 0;
  float4 pa, pb, pc;

  for (int t = 0; t < T2; t++){
    // ---- gather previous h of this batch element via 4-lane shfl ----
    float h_all[12];
    #pragma unroll
    for (int qp = 0; qp < 4; qp++){
      int src = (lane & ~3) | qp;
      h_all[3*qp+0] = __shfl_sync(0xffffffffu, hl0, src);
      h_all[3*qp+1] = __shfl_sync(0xffffffffu, hl1, src);
      h_all[3*qp+2] = __shfl_sync(0xffffffffu, hl2, src);
    }
    u64 xv[12];
    #pragma unroll
    for (int m = 0; m < 6; m++) xv[6+m] = pk2(h_all[2*m], h_all[2*m+1]);

    // ---- input availability; on starvation rebuild a 2-step cushion ----
    if (l > 0 && last_in < t+1){
      int tgt = t+3; if (tgt > T2) tgt = T2;
      do { last_in = ld_acq(flag_in); } while (last_in < tgt);
    }
    // early refresh (latency hides under FMA burst); consumed after burst
    int fut = last_in;
    if (l > 0 && t+1 < T2 && last_in < t+3) fut = ld_acq(flag_in);

    float4 xa, xb, xc;
    if (have){ xa = pa; xb = pb; xc = pc; }
    else {
      const float* src = (l == 0) ? (g_feat + (size_t)t*BH + b*12)
                                  : (ringi + (size_t)(t & RM)*BH + b*12);
      xa = __ldcg((const float4*)(src));
      xb = __ldcg((const float4*)(src + 4));
      xc = __ldcg((const float4*)(src + 8));
    }
    xv[0] = pk2(xa.x, xa.y); xv[1] = pk2(xa.z, xa.w);
    xv[2] = pk2(xb.x, xb.y); xv[3] = pk2(xb.z, xb.w);
    xv[4] = pk2(xc.x, xc.y); xv[5] = pk2(xc.z, xc.w);

    // ---- 12 gate pre-activations (4 gates x 3 cells) ----
    float gv[12];
    #pragma unroll
    for (int j = 0; j < 3; j++){
      #pragma unroll
      for (int g4 = 0; g4 < 4; g4++){
        const ulonglong2* wrow = (const ulonglong2*)(&wpk[g4*12 + 3*q + j][0]);
        u64 acc = 0ull;
        #pragma unroll
        for (int kq = 0; kq < 6; kq++){
          ulonglong2 wv = wrow[kq];
          ffma2(acc, wv.x, xv[2*kq]);
          ffma2(acc, wv.y, xv[2*kq+1]);
        }
        float lo, hi; upk2(acc, lo, hi);
        gv[j*4+g4] = lo + hi + br[j*4+g4];
      }
    }

    // ---- prefetch input for t+1 (cushion makes this deterministic) ----
    if (fut > last_in) last_in = fut;
    have = 0;
    if (t+1 < T2 && (l == 0 || last_in >= t+2)){
      const float* src2 = (l == 0) ? (g_feat + (size_t)(t+1)*BH + b*12)
                                   : (ringi + (size_t)((t+1) & RM)*BH + b*12);
      pa = __ldcg((const float4*)(src2));
      pb = __ldcg((const float4*)(src2 + 4));
      pc = __ldcg((const float4*)(src2 + 8));
      have = 1;
    }

    // ---- activations + cell update ----
    {
      float ig = sigf(gv[0]), fg = sigf(gv[1]), zg = tanh_(gv[2]), og = sigf(gv[3]);
      c0 = fg*c0 + ig*zg; hl0 = og*tanh_(c0);
    }
    {
      float ig = sigf(gv[4]), fg = sigf(gv[5]), zg = tanh_(gv[6]), og = sigf(gv[7]);
      c1 = fg*c1 + ig*zg; hl1 = og*tanh_(c1);
    }
    {
      float ig = sigf(gv[8]), fg = sigf(gv[9]), zg = tanh_(gv[10]), og = sigf(gv[11]);
      c2 = fg*c2 + ig*zg; hl2 = og*tanh_(c2);
    }

    // ---- publish ----
    if (l < LL-1){
      if (t >= RING && last_out + RING < t+1){
        do { last_out = ld_acq(flag_out); } while (last_out + RING < t+1);
      }
      float* dst = ringo + (size_t)(t & RM)*BH + b*12 + 3*q;
      __stcg(dst,     hl0);
      __stcg(dst + 1, hl1);
      __stcg(dst + 2, hl2);
    }
    __syncwarp();
    if (lane == 0) st_rel(flag_me, t+1);
  }

  int base = l*BH + b*12 + 3*q;
  g_hlast[base]     = hl0;
  g_hlast[base + 1] = hl1;
  g_hlast[base + 2] = hl2;
}

// ---------------- head: lin1/lin2 -> out, mu, softplus(sigma) ----------------
__global__ void k_head(const float* __restrict__ l1w, const float* __restrict__ l1b,
                       const float* __restrict__ l2w, const float* __restrict__ l2b,
                       const float* __restrict__ muw, const float* __restrict__ mub,
                       const float* __restrict__ sgw, const float* __restrict__ sgb,
                       float* __restrict__ out){
  int idx = blockIdx.x*blockDim.x + threadIdx.x;
  if (idx >= BB*LL) return;
  int b = idx / LL, l = idx % LL;
  const float* hv = g_hlast + l*BH + b*12;
  float h0[12], h1[12], h2[12];
  #pragma unroll
  for (int k = 0; k < 12; k++) h0[k] = hv[k];
  #pragma unroll
  for (int i = 0; i < 12; i++){
    float a = l1b[i];
    #pragma unroll
    for (int j = 0; j < 12; j++) a += l1w[i*12+j]*h0[j];
    h1[i] = fmaxf(a, 0.f);
  }
  #pragma unroll
  for (int i = 0; i < 12; i++){
    float a = l2b[i];
    #pragma unroll
    for (int j = 0; j < 12; j++) a += l2w[i*12+j]*h1[j];
    h2[i] = fmaxf(a, 0.f);
  }
  int base = (b*LL + l)*12;
  #pragma unroll
  for (int i = 0; i < 12; i++) out[base + i] = h2[i];
  #pragma unroll
  for (int i = 0; i < 12; i++){
    float a = mub[i];
    #pragma unroll
    for (int j = 0; j < 12; j++) a += muw[i*12+j]*h2[j];
    out[OUTSZ + base + i] = a;
  }
  #pragma unroll
  for (int i = 0; i < 12; i++){
    float a = sgb[i];
    #pragma unroll
    for (int j = 0; j < 12; j++) a += sgw[i*12+j]*h2[j];
    out[2*OUTSZ + base + i] = fmaxf(a, 0.f) + log1pf(__expf(-fabsf(a)));
  }
}

extern "C" void kernel_launch(void* const* d_in, const int* in_sizes, int n_in,
                              void* d_out, int out_size) {
  const float* x     = (const float*)d_in[0];
  const float* c1w   = (const float*)d_in[1];
  const float* c1b   = (const float*)d_in[2];
  const float* bn1g  = (const float*)d_in[3];
  const float* bn1b  = (const float*)d_in[4];
  const float* c2w   = (const float*)d_in[5];
  const float* c2b   = (const float*)d_in[6];
  const float* bn2g  = (const float*)d_in[7];
  const float* bn2b  = (const float*)d_in[8];
  const float* aw    = (const float*)d_in[9];
  const float* ab    = (const float*)d_in[10];
  const float* wih   = (const float*)d_in[11];
  const float* whh   = (const float*)d_in[12];
  const float* bih   = (const float*)d_in[13];
  const float* bhh   = (const float*)d_in[14];
  const float* l1w   = (const float*)d_in[15];
  const float* l1b   = (const float*)d_in[16];
  const float* l2w   = (const float*)d_in[17];
  const float* l2b   = (const float*)d_in[18];
  const float* muw   = (const float*)d_in[19];
  const float* mub   = (const float*)d_in[20];
  const float* sgw   = (const float*)d_in[21];
  const float* sgb   = (const float*)d_in[22];
  float* out = (float*)d_out;

  k_init<<<1, 1024>>>();
  k_conv1<<<BB, 256>>>(x, c1w, c1b);
  k_conv2<<<BB, 256>>>(c2w, c2b, bn1g, bn1b);
  k_attn<<<BB, 256>>>(bn2g, bn2b, aw, ab);
  k_lstm<<<LL, 256>>>(wih, whh, bih, bhh);
  k_head<<<(BB*LL + 127)/128, 128>>>(l1w, l1b, l2w, l2b, muw, mub, sgw, sgb, out);
}

// round 7
// speedup vs baseline: 1.1727x; 1.1727x over previous
#include <cuda_runtime.h>

typedef unsigned long long u64;

#define BB   64
#define TIN  1024
#define T1   1020
#define T2   1016
#define HH   12
#define LL   120
#define GG   48
#define RING 64
#define RM   (RING-1)
#define BH   (BB*HH)     /* 768 */
#define OUTSZ (BB*LL*HH) /* 92160 */
#define NW   8           /* warps per layer CTA */

// ---------------- device scratch (static, no allocation) ----------------
__device__ float g_y1[BB*6*T1];
__device__ float g_y2[BB*6*T2];
__device__ float g_part1[BB*12];
__device__ float g_part2[BB*12];
__device__ float g_feat[T2*BH];
__device__ float g_ring[(LL-1)*RING*BH];
__device__ float g_hlast[LL*BH];
__device__ int   g_progress[LL*NW];

// ---------------- helpers ----------------
__device__ __forceinline__ int ld_acq(const int* p){
  int v; asm volatile("ld.acquire.gpu.b32 %0, [%1];" : "=r"(v) : "l"(p)); return v;
}
__device__ __forceinline__ void st_rel(int* p, int v){
  asm volatile("st.release.gpu.b32 [%0], %1;" :: "l"(p), "r"(v));
}
__device__ __forceinline__ u64 pk2(float lo, float hi){
  u64 r; asm("mov.b64 %0, {%1, %2};" : "=l"(r) : "f"(lo), "f"(hi)); return r;
}
__device__ __forceinline__ void upk2(u64 v, float& lo, float& hi){
  asm("mov.b64 {%0, %1}, %2;" : "=f"(lo), "=f"(hi) : "l"(v));
}
__device__ __forceinline__ void ffma2(u64& acc, u64 a, u64 b){
  asm("fma.rn.f32x2 %0, %1, %2, %0;" : "+l"(acc) : "l"(a), "l"(b));
}
__device__ __forceinline__ float sigf(float x){
  float e = __expf(-x); return __fdividef(1.f, 1.f + e);
}
__device__ __forceinline__ float tanh_(float x){
  float ax = fabsf(x);
  float e  = __expf(-2.f*ax);
  float t  = __fdividef(1.f - e, 1.f + e);
  return (x < 0.f) ? -t : t;
}

// ---------------- conv1 + batch-stat partials (+ pipeline-flag reset) ------
__global__ void k_conv1(const float* __restrict__ x, const float* __restrict__ w,
                        const float* __restrict__ bias){
  __shared__ float xs[6*TIN];
  __shared__ float ws[180];
  __shared__ float bs[6];
  __shared__ float red[12][8];
  int b = blockIdx.x, tid = threadIdx.x;
  if (b == 0){                       // flag reset (read only by later k_lstm)
    for (int i = tid; i < LL*NW; i += 256) g_progress[i] = 0;
  }
  for (int i = tid; i < 6*TIN; i += 256) xs[i] = x[b*6*TIN + i];
  for (int i = tid; i < 180;   i += 256) ws[i] = w[i];
  if (tid < 6) bs[tid] = bias[tid];
  __syncthreads();
  float s[6] = {0,0,0,0,0,0}, q[6] = {0,0,0,0,0,0};
  for (int t = tid; t < T1; t += 256){
    float acc[6];
    #pragma unroll
    for (int co = 0; co < 6; co++) acc[co] = bs[co];
    #pragma unroll
    for (int ci = 0; ci < 6; ci++){
      float xr[5];
      #pragma unroll
      for (int k = 0; k < 5; k++) xr[k] = xs[ci*TIN + t + k];
      #pragma unroll
      for (int co = 0; co < 6; co++){
        const float* wp = &ws[co*30 + ci*5];
        #pragma unroll
        for (int k = 0; k < 5; k++) acc[co] += xr[k]*wp[k];
      }
    }
    #pragma unroll
    for (int co = 0; co < 6; co++){
      g_y1[b*6*T1 + co*T1 + t] = acc[co];
      s[co] += acc[co]; q[co] += acc[co]*acc[co];
    }
  }
  int lane = tid & 31, wrp = tid >> 5;
  #pragma unroll
  for (int c = 0; c < 6; c++){
    float v = s[c], u = q[c];
    #pragma unroll
    for (int o = 16; o; o >>= 1){
      v += __shfl_down_sync(0xffffffffu, v, o);
      u += __shfl_down_sync(0xffffffffu, u, o);
    }
    if (lane == 0){ red[c][wrp] = v; red[6+c][wrp] = u; }
  }
  __syncthreads();
  if (tid < 12){
    float a = 0.f;
    #pragma unroll
    for (int w8 = 0; w8 < 8; w8++) a += red[tid][w8];
    g_part1[b*12 + tid] = a;
  }
}

// ---------------- bn1+relu -> conv2 + stat partials ----------------
__global__ void k_conv2(const float* __restrict__ w, const float* __restrict__ bias,
                        const float* __restrict__ gamma, const float* __restrict__ beta){
  __shared__ float xs[6*T1];
  __shared__ float ws[180];
  __shared__ float bs[6];
  __shared__ float stt[12];
  __shared__ float sc[6], sh[6];
  __shared__ float red[12][8];
  int b = blockIdx.x, tid = threadIdx.x;
  if (tid < 12){
    float a = 0.f;
    for (int bb = 0; bb < BB; bb++) a += g_part1[bb*12 + tid];
    stt[tid] = a;
  }
  for (int i = tid; i < 180; i += 256) ws[i] = w[i];
  if (tid < 6) bs[tid] = bias[tid];
  __syncthreads();
  if (tid < 6){
    float inv  = 1.f / (64.f * 1020.f);
    float mean = stt[tid]*inv;
    float var  = stt[6+tid]*inv - mean*mean;
    float scl  = gamma[tid]*rsqrtf(var + 1e-5f);
    sc[tid] = scl; sh[tid] = beta[tid] - mean*scl;
  }
  __syncthreads();
  for (int i = tid; i < 6*T1; i += 256){
    int c = i / T1;
    float v = g_y1[b*6*T1 + i]*sc[c] + sh[c];
    xs[i] = fmaxf(v, 0.f);
  }
  __syncthreads();
  float s[6] = {0,0,0,0,0,0}, q[6] = {0,0,0,0,0,0};
  for (int t = tid; t < T2; t += 256){
    float acc[6];
    #pragma unroll
    for (int co = 0; co < 6; co++) acc[co] = bs[co];
    #pragma unroll
    for (int ci = 0; ci < 6; ci++){
      float xr[5];
      #pragma unroll
      for (int k = 0; k < 5; k++) xr[k] = xs[ci*T1 + t + k];
      #pragma unroll
      for (int co = 0; co < 6; co++){
        const float* wp = &ws[co*30 + ci*5];
        #pragma unroll
        for (int k = 0; k < 5; k++) acc[co] += xr[k]*wp[k];
      }
    }
    #pragma unroll
    for (int co = 0; co < 6; co++){
      g_y2[b*6*T2 + co*T2 + t] = acc[co];
      s[co] += acc[co]; q[co] += acc[co]*acc[co];
    }
  }
  int lane = tid & 31, wrp = tid >> 5;
  #pragma unroll
  for (int c = 0; c < 6; c++){
    float v = s[c], u = q[c];
    #pragma unroll
    for (int o = 16; o; o >>= 1){
      v += __shfl_down_sync(0xffffffffu, v, o);
      u += __shfl_down_sync(0xffffffffu, u, o);
    }
    if (lane == 0){ red[c][wrp] = v; red[6+c][wrp] = u; }
  }
  __syncthreads();
  if (tid < 12){
    float a = 0.f;
    #pragma unroll
    for (int w8 = 0; w8 < 8; w8++) a += red[tid][w8];
    g_part2[b*12 + tid] = a;
  }
}

// ---------------- bn2+relu -> attn projection -> feat[t][b][h] ----------------
__global__ void k_attn(const float* __restrict__ gamma, const float* __restrict__ beta,
                       const float* __restrict__ aw, const float* __restrict__ ab){
  __shared__ float xs[6*T2];
  __shared__ float stt[12];
  __shared__ float sc[6], sh[6];
  __shared__ float aws[72];
  __shared__ float abv[12];
  int b = blockIdx.x, tid = threadIdx.x;
  if (tid < 12){
    float a = 0.f;
    for (int bb = 0; bb < BB; bb++) a += g_part2[bb*12 + tid];
    stt[tid] = a;
  }
  if (tid < 72) aws[tid] = aw[tid];
  if (tid < 12) abv[tid] = ab[tid];
  __syncthreads();
  if (tid < 6){
    float inv  = 1.f / (64.f * 1016.f);
    float mean = stt[tid]*inv;
    float var  = stt[6+tid]*inv - mean*mean;
    float scl  = gamma[tid]*rsqrtf(var + 1e-5f);
    sc[tid] = scl; sh[tid] = beta[tid] - mean*scl;
  }
  __syncthreads();
  for (int i = tid; i < 6*T2; i += 256){
    int c = i / T2;
    float v = g_y2[b*6*T2 + i]*sc[c] + sh[c];
    xs[i] = fmaxf(v, 0.f);
  }
  __syncthreads();
  for (int i = tid; i < T2*HH; i += 256){
    int t = i / HH, h = i % HH;
    float acc = abv[h];
    #pragma unroll
    for (int c = 0; c < 6; c++) acc += xs[c*T2 + t]*aws[h*6 + c];
    g_feat[t*BH + b*12 + h] = fmaxf(acc, 0.f);
  }
}

// ---------------- pipelined 120-layer LSTM, warp-granular ----------------
// 1 layer per CTA. Lane-group of 4 owns one batch element (b = tid>>2,
// q = tid&3, cells 3q..3q+2); h exchanged via shfl. Warp w syncs only with
// warp w of neighbor layers via per-warp release/acquire flags (R3 logic).
// NEW: weight rows of gates 0,1 (6 of 12 rows) are cached in registers,
// halving per-step smem LDS traffic (72 -> 36 LDS.128 per thread).
__global__ void __launch_bounds__(256,1) k_lstm(const float* __restrict__ wih,
                                                const float* __restrict__ whh,
                                                const float* __restrict__ bih,
                                                const float* __restrict__ bhh){
  int l = blockIdx.x, tid = threadIdx.x;
  int lane = tid & 31;
  int wz   = tid >> 5;          // warp id 0..7
  int q    = lane & 3;          // quarter within batch group
  int b    = tid >> 2;          // batch element 0..63

  __shared__ __align__(16) u64 wpk[GG][12];  // packed {w_k,w_{k+1}} per gate row over [x;h]

  const float* wi = wih + l*576;
  const float* wh = whh + l*576;
  for (int i = tid; i < GG*12; i += 256){
    int gg = i / 12, kp = i % 12;
    float w0, w1;
    if (kp < 6){ w0 = wi[gg*12 + 2*kp];      w1 = wi[gg*12 + 2*kp + 1];  }
    else       { w0 = wh[gg*12 + 2*kp - 12]; w1 = wh[gg*12 + 2*kp - 11]; }
    wpk[gg][kp] = pk2(w0, w1);
  }
  __syncthreads();

  // register-cache rows of gates 0 and 1 (cells 3q..3q+2): 6 rows x 12 u64
  u64 wr[6][12];
  #pragma unroll
  for (int g4 = 0; g4 < 2; g4++)
    #pragma unroll
    for (int j = 0; j < 3; j++)
      #pragma unroll
      for (int k = 0; k < 12; k++)
        wr[g4*3+j][k] = wpk[g4*12 + 3*q + j][k];

  // biases for this thread's 12 gate rows (row = gate*12 + 3q + j)
  float br[12];
  #pragma unroll
  for (int j = 0; j < 3; j++){
    #pragma unroll
    for (int g4 = 0; g4 < 4; g4++){
      int row = g4*12 + 3*q + j;
      br[j*4+g4] = bih[l*GG + row] + bhh[l*GG + row];
    }
  }

  float c0 = 0.f, c1 = 0.f, c2 = 0.f;
  float hl0 = 0.f, hl1 = 0.f, hl2 = 0.f;
  float*       ringo = (l < LL-1) ? (g_ring + (size_t)l*(RING*BH)) : (float*)0;
  const float* ringi = (l > 0)    ? (g_ring + (size_t)(l-1)*(RING*BH)) : (const float*)0;
  const int* flag_in  = (l > 0)    ? &g_progress[(l-1)*NW + wz] : (const int*)0;
  const int* flag_out = (l < LL-1) ? &g_progress[(l+1)*NW + wz] : (const int*)0;
  int* flag_me = &g_progress[l*NW + wz];

  int last_in = 0, last_out = 0;
  int have = 0;
  float4 pa, pb, pc;

  for (int t = 0; t < T2; t++){
    // ---- gather previous h of this batch element via 4-lane shfl ----
    float h_all[12];
    #pragma unroll
    for (int qp = 0; qp < 4; qp++){
      int src = (lane & ~3) | qp;
      h_all[3*qp+0] = __shfl_sync(0xffffffffu, hl0, src);
      h_all[3*qp+1] = __shfl_sync(0xffffffffu, hl1, src);
      h_all[3*qp+2] = __shfl_sync(0xffffffffu, hl2, src);
    }
    u64 xv[12];
    #pragma unroll
    for (int m = 0; m < 6; m++) xv[6+m] = pk2(h_all[2*m], h_all[2*m+1]);

    // ---- input availability (cached, monotonic) ----
    if (l > 0 && last_in < t+1){
      do { last_in = ld_acq(flag_in); } while (last_in < t+1);
    }
    // early refresh for next-step prefetch (latency hides under FMA burst)
    int fut = last_in;
    if (l > 0 && t+1 < T2 && last_in < t+2) fut = ld_acq(flag_in);

    float4 xa, xb, xc;
    if (have){ xa = pa; xb = pb; xc = pc; }
    else {
      const float* src = (l == 0) ? (g_feat + (size_t)t*BH + b*12)
                                  : (ringi + (size_t)(t & RM)*BH + b*12);
      xa = __ldcg((const float4*)(src));
      xb = __ldcg((const float4*)(src + 4));
      xc = __ldcg((const float4*)(src + 8));
    }
    xv[0] = pk2(xa.x, xa.y); xv[1] = pk2(xa.z, xa.w);
    xv[2] = pk2(xb.x, xb.y); xv[3] = pk2(xb.z, xb.w);
    xv[4] = pk2(xc.x, xc.y); xv[5] = pk2(xc.z, xc.w);

    // ---- 12 gate pre-activations: gates 0,1 from registers ----
    float gv[12];
    #pragma unroll
    for (int g4 = 0; g4 < 2; g4++){
      #pragma unroll
      for (int j = 0; j < 3; j++){
        u64 acc = 0ull;
        #pragma unroll
        for (int k = 0; k < 12; k++) ffma2(acc, wr[g4*3+j][k], xv[k]);
        float lo, hi; upk2(acc, lo, hi);
        gv[j*4+g4] = lo + hi + br[j*4+g4];
      }
    }
    // ---- gates 2,3 from shared memory ----
    #pragma unroll
    for (int g4 = 2; g4 < 4; g4++){
      #pragma unroll
      for (int j = 0; j < 3; j++){
        const ulonglong2* wrow = (const ulonglong2*)(&wpk[g4*12 + 3*q + j][0]);
        u64 acc = 0ull;
        #pragma unroll
        for (int kq = 0; kq < 6; kq++){
          ulonglong2 wv = wrow[kq];
          ffma2(acc, wv.x, xv[2*kq]);
          ffma2(acc, wv.y, xv[2*kq+1]);
        }
        float lo, hi; upk2(acc, lo, hi);
        gv[j*4+g4] = lo + hi + br[j*4+g4];
      }
    }

    // ---- prefetch input for t+1 ----
    if (fut > last_in) last_in = fut;
    have = 0;
    if (t+1 < T2 && (l == 0 || last_in >= t+2)){
      const float* src2 = (l == 0) ? (g_feat + (size_t)(t+1)*BH + b*12)
                                   : (ringi + (size_t)((t+1) & RM)*BH + b*12);
      pa = __ldcg((const float4*)(src2));
      pb = __ldcg((const float4*)(src2 + 4));
      pc = __ldcg((const float4*)(src2 + 8));
      have = 1;
    }

    // ---- activations + cell update ----
    {
      float ig = sigf(gv[0]), fg = sigf(gv[1]), zg = tanh_(gv[2]), og = sigf(gv[3]);
      c0 = fg*c0 + ig*zg; hl0 = og*tanh_(c0);
    }
    {
      float ig = sigf(gv[4]), fg = sigf(gv[5]), zg = tanh_(gv[6]), og = sigf(gv[7]);
      c1 = fg*c1 + ig*zg; hl1 = og*tanh_(c1);
    }
    {
      float ig = sigf(gv[8]), fg = sigf(gv[9]), zg = tanh_(gv[10]), og = sigf(gv[11]);
      c2 = fg*c2 + ig*zg; hl2 = og*tanh_(c2);
    }

    // ---- publish ----
    if (l < LL-1){
      if (t >= RING && last_out + RING < t+1){
        do { last_out = ld_acq(flag_out); } while (last_out + RING < t+1);
      }
      float* dst = ringo + (size_t)(t & RM)*BH + b*12 + 3*q;
      __stcg(dst,     hl0);
      __stcg(dst + 1, hl1);
      __stcg(dst + 2, hl2);
    }
    __syncwarp();
    if (lane == 0) st_rel(flag_me, t+1);
  }

  int base = l*BH + b*12 + 3*q;
  g_hlast[base]     = hl0;
  g_hlast[base + 1] = hl1;
  g_hlast[base + 2] = hl2;
}

// ---------------- head: lin1/lin2 -> out, mu, softplus(sigma) ----------------
__global__ void k_head(const float* __restrict__ l1w, const float* __restrict__ l1b,
                       const float* __restrict__ l2w, const float* __restrict__ l2b,
                       const float* __restrict__ muw, const float* __restrict__ mub,
                       const float* __restrict__ sgw, const float* __restrict__ sgb,
                       float* __restrict__ out){
  int idx = blockIdx.x*blockDim.x + threadIdx.x;
  if (idx >= BB*LL) return;
  int b = idx / LL, l = idx % LL;
  const float* hv = g_hlast + l*BH + b*12;
  float h0[12], h1[12], h2[12];
  #pragma unroll
  for (int k = 0; k < 12; k++) h0[k] = hv[k];
  #pragma unroll
  for (int i = 0; i < 12; i++){
    float a = l1b[i];
    #pragma unroll
    for (int j = 0; j < 12; j++) a += l1w[i*12+j]*h0[j];
    h1[i] = fmaxf(a, 0.f);
  }
  #pragma unroll
  for (int i = 0; i < 12; i++){
    float a = l2b[i];
    #pragma unroll
    for (int j = 0; j < 12; j++) a += l2w[i*12+j]*h1[j];
    h2[i] = fmaxf(a, 0.f);
  }
  int base = (b*LL + l)*12;
  #pragma unroll
  for (int i = 0; i < 12; i++) out[base + i] = h2[i];
  #pragma unroll
  for (int i = 0; i < 12; i++){
    float a = mub[i];
    #pragma unroll
    for (int j = 0; j < 12; j++) a += muw[i*12+j]*h2[j];
    out[OUTSZ + base + i] = a;
  }
  #pragma unroll
  for (int i = 0; i < 12; i++){
    float a = sgb[i];
    #pragma unroll
    for (int j = 0; j < 12; j++) a += sgw[i*12+j]*h2[j];
    out[2*OUTSZ + base + i] = fmaxf(a, 0.f) + log1pf(__expf(-fabsf(a)));
  }
}

extern "C" void kernel_launch(void* const* d_in, const int* in_sizes, int n_in,
                              void* d_out, int out_size) {
  const float* x     = (const float*)d_in[0];
  const float* c1w   = (const float*)d_in[1];
  const float* c1b   = (const float*)d_in[2];
  const float* bn1g  = (const float*)d_in[3];
  const float* bn1b  = (const float*)d_in[4];
  const float* c2w   = (const float*)d_in[5];
  const float* c2b   = (const float*)d_in[6];
  const float* bn2g  = (const float*)d_in[7];
  const float* bn2b  = (const float*)d_in[8];
  const float* aw    = (const float*)d_in[9];
  const float* ab    = (const float*)d_in[10];
  const float* wih   = (const float*)d_in[11];
  const float* whh   = (const float*)d_in[12];
  const float* bih   = (const float*)d_in[13];
  const float* bhh   = (const float*)d_in[14];
  const float* l1w   = (const float*)d_in[15];
  const float* l1b   = (const float*)d_in[16];
  const float* l2w   = (const float*)d_in[17];
  const float* l2b   = (const float*)d_in[18];
  const float* muw   = (const float*)d_in[19];
  const float* mub   = (const float*)d_in[20];
  const float* sgw   = (const float*)d_in[21];
  const float* sgb   = (const float*)d_in[22];
  float* out = (float*)d_out;

  k_conv1<<<BB, 256>>>(x, c1w, c1b);
  k_conv2<<<BB, 256>>>(c2w, c2b, bn1g, bn1b);
  k_attn<<<BB, 256>>>(bn2g, bn2b, aw, ab);
  k_lstm<<<LL, 256>>>(wih, whh, bih, bhh);
  k_head<<<(BB*LL + 127)/128, 128>>>(l1w, l1b, l2w, l2b, muw, mub, sgw, sgb, out);
}

// round 9
// speedup vs baseline: 1.2009x; 1.0240x over previous
#include <cuda_runtime.h>

typedef unsigned long long u64;

#define BB   64
#define TIN  1024
#define T1   1020
#define T2   1016
#define HH   12
#define LL   120
#define GG   48
#define RING 64
#define RM   (RING-1)
#define BH   (BB*HH)     /* 768 */
#define OUTSZ (BB*LL*HH) /* 92160 */
#define NW   8           /* warps per layer CTA */

// ---------------- device scratch (static, no allocation) ----------------
__device__ float g_y1[BB*6*T1];
__device__ float g_y2[BB*6*T2];
__device__ float g_part1[BB*12];
__device__ float g_part2[BB*12];
__device__ float g_feat[T2*BH];
__device__ float g_ring[(LL-1)*RING*BH];
__device__ float g_hlast[LL*BH];
__device__ int   g_progress[LL*NW];

// ---------------- helpers ----------------
__device__ __forceinline__ int ld_acq(const int* p){
  int v; asm volatile("ld.acquire.gpu.b32 %0, [%1];" : "=r"(v) : "l"(p)); return v;
}
__device__ __forceinline__ void st_rel(int* p, int v){
  asm volatile("st.release.gpu.b32 [%0], %1;" :: "l"(p), "r"(v));
}
__device__ __forceinline__ u64 pk2(float lo, float hi){
  u64 r; asm("mov.b64 %0, {%1, %2};" : "=l"(r) : "f"(lo), "f"(hi)); return r;
}
__device__ __forceinline__ void upk2(u64 v, float& lo, float& hi){
  asm("mov.b64 {%0, %1}, %2;" : "=f"(lo), "=f"(hi) : "l"(v));
}
__device__ __forceinline__ void ffma2(u64& acc, u64 a, u64 b){
  asm("fma.rn.f32x2 %0, %1, %2, %0;" : "+l"(acc) : "l"(a), "l"(b));
}
// hardware tanh (sm_75+): single MUFU op
__device__ __forceinline__ float tanhfast(float x){
  float y; asm("tanh.approx.f32 %0, %1;" : "=f"(y) : "f"(x)); return y;
}
// exact versions kept for the (non-critical) head kernel
__device__ __forceinline__ float sigf(float x){
  float e = __expf(-x); return __fdividef(1.f, 1.f + e);
}

// ---------------- conv1 + batch-stat partials (+ pipeline-flag reset) ------
__global__ void k_conv1(const float* __restrict__ x, const float* __restrict__ w,
                        const float* __restrict__ bias){
  __shared__ float xs[6*TIN];
  __shared__ float ws[180];
  __shared__ float bs[6];
  __shared__ float red[12][8];
  int b = blockIdx.x, tid = threadIdx.x;
  if (b == 0){                       // flag reset (read only by later k_lstm)
    for (int i = tid; i < LL*NW; i += 256) g_progress[i] = 0;
  }
  for (int i = tid; i < 6*TIN; i += 256) xs[i] = x[b*6*TIN + i];
  for (int i = tid; i < 180;   i += 256) ws[i] = w[i];
  if (tid < 6) bs[tid] = bias[tid];
  __syncthreads();
  float s[6] = {0,0,0,0,0,0}, q[6] = {0,0,0,0,0,0};
  for (int t = tid; t < T1; t += 256){
    float acc[6];
    #pragma unroll
    for (int co = 0; co < 6; co++) acc[co] = bs[co];
    #pragma unroll
    for (int ci = 0; ci < 6; ci++){
      float xr[5];
      #pragma unroll
      for (int k = 0; k < 5; k++) xr[k] = xs[ci*TIN + t + k];
      #pragma unroll
      for (int co = 0; co < 6; co++){
        const float* wp = &ws[co*30 + ci*5];
        #pragma unroll
        for (int k = 0; k < 5; k++) acc[co] += xr[k]*wp[k];
      }
    }
    #pragma unroll
    for (int co = 0; co < 6; co++){
      g_y1[b*6*T1 + co*T1 + t] = acc[co];
      s[co] += acc[co]; q[co] += acc[co]*acc[co];
    }
  }
  int lane = tid & 31, wrp = tid >> 5;
  #pragma unroll
  for (int c = 0; c < 6; c++){
    float v = s[c], u = q[c];
    #pragma unroll
    for (int o = 16; o; o >>= 1){
      v += __shfl_down_sync(0xffffffffu, v, o);
      u += __shfl_down_sync(0xffffffffu, u, o);
    }
    if (lane == 0){ red[c][wrp] = v; red[6+c][wrp] = u; }
  }
  __syncthreads();
  if (tid < 12){
    float a = 0.f;
    #pragma unroll
    for (int w8 = 0; w8 < 8; w8++) a += red[tid][w8];
    g_part1[b*12 + tid] = a;
  }
}

// ---------------- bn1+relu -> conv2 + stat partials ----------------
__global__ void k_conv2(const float* __restrict__ w, const float* __restrict__ bias,
                        const float* __restrict__ gamma, const float* __restrict__ beta){
  __shared__ float xs[6*T1];
  __shared__ float ws[180];
  __shared__ float bs[6];
  __shared__ float stt[12];
  __shared__ float sc[6], sh[6];
  __shared__ float red[12][8];
  int b = blockIdx.x, tid = threadIdx.x;
  if (tid < 12){
    float a = 0.f;
    for (int bb = 0; bb < BB; bb++) a += g_part1[bb*12 + tid];
    stt[tid] = a;
  }
  for (int i = tid; i < 180; i += 256) ws[i] = w[i];
  if (tid < 6) bs[tid] = bias[tid];
  __syncthreads();
  if (tid < 6){
    float inv  = 1.f / (64.f * 1020.f);
    float mean = stt[tid]*inv;
    float var  = stt[6+tid]*inv - mean*mean;
    float scl  = gamma[tid]*rsqrtf(var + 1e-5f);
    sc[tid] = scl; sh[tid] = beta[tid] - mean*scl;
  }
  __syncthreads();
  for (int i = tid; i < 6*T1; i += 256){
    int c = i / T1;
    float v = g_y1[b*6*T1 + i]*sc[c] + sh[c];
    xs[i] = fmaxf(v, 0.f);
  }
  __syncthreads();
  float s[6] = {0,0,0,0,0,0}, q[6] = {0,0,0,0,0,0};
  for (int t = tid; t < T2; t += 256){
    float acc[6];
    #pragma unroll
    for (int co = 0; co < 6; co++) acc[co] = bs[co];
    #pragma unroll
    for (int ci = 0; ci < 6; ci++){
      float xr[5];
      #pragma unroll
      for (int k = 0; k < 5; k++) xr[k] = xs[ci*T1 + t + k];
      #pragma unroll
      for (int co = 0; co < 6; co++){
        const float* wp = &ws[co*30 + ci*5];
        #pragma unroll
        for (int k = 0; k < 5; k++) acc[co] += xr[k]*wp[k];
      }
    }
    #pragma unroll
    for (int co = 0; co < 6; co++){
      g_y2[b*6*T2 + co*T2 + t] = acc[co];
      s[co] += acc[co]; q[co] += acc[co]*acc[co];
    }
  }
  int lane = tid & 31, wrp = tid >> 5;
  #pragma unroll
  for (int c = 0; c < 6; c++){
    float v = s[c], u = q[c];
    #pragma unroll
    for (int o = 16; o; o >>= 1){
      v += __shfl_down_sync(0xffffffffu, v, o);
      u += __shfl_down_sync(0xffffffffu, u, o);
    }
    if (lane == 0){ red[c][wrp] = v; red[6+c][wrp] = u; }
  }
  __syncthreads();
  if (tid < 12){
    float a = 0.f;
    #pragma unroll
    for (int w8 = 0; w8 < 8; w8++) a += red[tid][w8];
    g_part2[b*12 + tid] = a;
  }
}

// ---------------- bn2+relu -> attn projection -> feat[t][b][h] ----------------
__global__ void k_attn(const float* __restrict__ gamma, const float* __restrict__ beta,
                       const float* __restrict__ aw, const float* __restrict__ ab){
  __shared__ float xs[6*T2];
  __shared__ float stt[12];
  __shared__ float sc[6], sh[6];
  __shared__ float aws[72];
  __shared__ float abv[12];
  int b = blockIdx.x, tid = threadIdx.x;
  if (tid < 12){
    float a = 0.f;
    for (int bb = 0; bb < BB; bb++) a += g_part2[bb*12 + tid];
    stt[tid] = a;
  }
  if (tid < 72) aws[tid] = aw[tid];
  if (tid < 12) abv[tid] = ab[tid];
  __syncthreads();
  if (tid < 6){
    float inv  = 1.f / (64.f * 1016.f);
    float mean = stt[tid]*inv;
    float var  = stt[6+tid]*inv - mean*mean;
    float scl  = gamma[tid]*rsqrtf(var + 1e-5f);
    sc[tid] = scl; sh[tid] = beta[tid] - mean*scl;
  }
  __syncthreads();
  for (int i = tid; i < 6*T2; i += 256){
    int c = i / T2;
    float v = g_y2[b*6*T2 + i]*sc[c] + sh[c];
    xs[i] = fmaxf(v, 0.f);
  }
  __syncthreads();
  for (int i = tid; i < T2*HH; i += 256){
    int t = i / HH, h = i % HH;
    float acc = abv[h];
    #pragma unroll
    for (int c = 0; c < 6; c++) acc += xs[c*T2 + t]*aws[h*6 + c];
    g_feat[t*BH + b*12 + h] = fmaxf(acc, 0.f);
  }
}

// ---------------- pipelined 120-layer LSTM, warp-granular ----------------
// 1 layer per CTA. Lane-group of 4 owns one batch element (b = tid>>2,
// q = tid&3, cells 3q..3q+2); h exchanged via shfl. Warp w syncs only with
// warp w of neighbor layers via per-warp release/acquire flags (R3 logic).
// Weights of gates 0,1 register-cached (R6 win).
// NEW (R7): hardware tanh.approx for all activations; sigmoid gates use
// sigma(x)=0.5*tanh(x/2)+0.5 with the 0.5 pre-folded into the bias.
__global__ void __launch_bounds__(256,1) k_lstm(const float* __restrict__ wih,
                                                const float* __restrict__ whh,
                                                const float* __restrict__ bih,
                                                const float* __restrict__ bhh){
  int l = blockIdx.x, tid = threadIdx.x;
  int lane = tid & 31;
  int wz   = tid >> 5;          // warp id 0..7
  int q    = lane & 3;          // quarter within batch group
  int b    = tid >> 2;          // batch element 0..63

  __shared__ __align__(16) u64 wpk[GG][12];  // packed {w_k,w_{k+1}} per gate row over [x;h]

  const float* wi = wih + l*576;
  const float* wh = whh + l*576;
  for (int i = tid; i < GG*12; i += 256){
    int gg = i / 12, kp = i % 12;
    float w0, w1;
    if (kp < 6){ w0 = wi[gg*12 + 2*kp];      w1 = wi[gg*12 + 2*kp + 1];  }
    else       { w0 = wh[gg*12 + 2*kp - 12]; w1 = wh[gg*12 + 2*kp - 11]; }
    wpk[gg][kp] = pk2(w0, w1);
  }
  __syncthreads();

  // register-cache rows of gates 0 and 1 (cells 3q..3q+2): 6 rows x 12 u64
  u64 wr[6][12];
  #pragma unroll
  for (int g4 = 0; g4 < 2; g4++)
    #pragma unroll
    for (int j = 0; j < 3; j++)
      #pragma unroll
      for (int k = 0; k < 12; k++)
        wr[g4*3+j][k] = wpk[g4*12 + 3*q + j][k];

  // biases; gates 0,1,3 (sigmoid) pre-scaled by 0.5 for the tanh identity
  float br[12];
  #pragma unroll
  for (int j = 0; j < 3; j++){
    #pragma unroll
    for (int g4 = 0; g4 < 4; g4++){
      int row = g4*12 + 3*q + j;
      float bv = bih[l*GG + row] + bhh[l*GG + row];
      br[j*4+g4] = (g4 == 2) ? bv : 0.5f*bv;
    }
  }

  float c0 = 0.f, c1 = 0.f, c2 = 0.f;
  float hl0 = 0.f, hl1 = 0.f, hl2 = 0.f;
  float*       ringo = (l < LL-1) ? (g_ring + (size_t)l*(RING*BH)) : (float*)0;
  const float* ringi = (l > 0)    ? (g_ring + (size_t)(l-1)*(RING*BH)) : (const float*)0;
  const int* flag_in  = (l > 0)    ? &g_progress[(l-1)*NW + wz] : (const int*)0;
  const int* flag_out = (l < LL-1) ? &g_progress[(l+1)*NW + wz] : (const int*)0;
  int* flag_me = &g_progress[l*NW + wz];

  int last_in = 0, last_out = 0;
  int have = 0;
  float4 pa, pb, pc;

  for (int t = 0; t < T2; t++){
    // ---- gather previous h of this batch element via 4-lane shfl ----
    float h_all[12];
    #pragma unroll
    for (int qp = 0; qp < 4; qp++){
      int src = (lane & ~3) | qp;
      h_all[3*qp+0] = __shfl_sync(0xffffffffu, hl0, src);
      h_all[3*qp+1] = __shfl_sync(0xffffffffu, hl1, src);
      h_all[3*qp+2] = __shfl_sync(0xffffffffu, hl2, src);
    }
    u64 xv[12];
    #pragma unroll
    for (int m = 0; m < 6; m++) xv[6+m] = pk2(h_all[2*m], h_all[2*m+1]);

    // ---- input availability (cached, monotonic) ----
    if (l > 0 && last_in < t+1){
      do { last_in = ld_acq(flag_in); } while (last_in < t+1);
    }
    // early refresh for next-step prefetch (latency hides under FMA burst)
    int fut = last_in;
    if (l > 0 && t+1 < T2 && last_in < t+2) fut = ld_acq(flag_in);

    float4 xa, xb, xc;
    if (have){ xa = pa; xb = pb; xc = pc; }
    else {
      const float* src = (l == 0) ? (g_feat + (size_t)t*BH + b*12)
                                  : (ringi + (size_t)(t & RM)*BH + b*12);
      xa = __ldcg((const float4*)(src));
      xb = __ldcg((const float4*)(src + 4));
      xc = __ldcg((const float4*)(src + 8));
    }
    xv[0] = pk2(xa.x, xa.y); xv[1] = pk2(xa.z, xa.w);
    xv[2] = pk2(xb.x, xb.y); xv[3] = pk2(xb.z, xb.w);
    xv[4] = pk2(xc.x, xc.y); xv[5] = pk2(xc.z, xc.w);

    // ---- 12 gate pre-activations: gates 0,1 from registers ----
    // sigmoid gates (g4 = 0,1,3): gv = 0.5*(w.x+b)  [bias pre-scaled]
    // tanh gate    (g4 = 2):      gv =      w.x+b
    float gv[12];
    #pragma unroll
    for (int g4 = 0; g4 < 2; g4++){
      #pragma unroll
      for (int j = 0; j < 3; j++){
        u64 acc = 0ull;
        #pragma unroll
        for (int k = 0; k < 12; k++) ffma2(acc, wr[g4*3+j][k], xv[k]);
        float lo, hi; upk2(acc, lo, hi);
        gv[j*4+g4] = fmaf(lo + hi, 0.5f, br[j*4+g4]);
      }
    }
    // ---- gates 2,3 from shared memory ----
    #pragma unroll
    for (int g4 = 2; g4 < 4; g4++){
      #pragma unroll
      for (int j = 0; j < 3; j++){
        const ulonglong2* wrow = (const ulonglong2*)(&wpk[g4*12 + 3*q + j][0]);
        u64 acc = 0ull;
        #pragma unroll
        for (int kq = 0; kq < 6; kq++){
          ulonglong2 wv = wrow[kq];
          ffma2(acc, wv.x, xv[2*kq]);
          ffma2(acc, wv.y, xv[2*kq+1]);
        }
        float lo, hi; upk2(acc, lo, hi);
        gv[j*4+g4] = (g4 == 2) ? (lo + hi + br[j*4+g4])
                               : fmaf(lo + hi, 0.5f, br[j*4+g4]);
      }
    }

    // ---- prefetch input for t+1 ----
    if (fut > last_in) last_in = fut;
    have = 0;
    if (t+1 < T2 && (l == 0 || last_in >= t+2)){
      const float* src2 = (l == 0) ? (g_feat + (size_t)(t+1)*BH + b*12)
                                   : (ringi + (size_t)((t+1) & RM)*BH + b*12);
      pa = __ldcg((const float4*)(src2));
      pb = __ldcg((const float4*)(src2 + 4));
      pc = __ldcg((const float4*)(src2 + 8));
      have = 1;
    }

    // ---- activations (HW tanh) + cell update ----
    {
      float ig = fmaf(0.5f, tanhfast(gv[0]), 0.5f);
      float fg = fmaf(0.5f, tanhfast(gv[1]), 0.5f);
      float zg = tanhfast(gv[2]);
      float og = fmaf(0.5f, tanhfast(gv[3]), 0.5f);
      c0 = fg*c0 + ig*zg; hl0 = og*tanhfast(c0);
    }
    {
      float ig = fmaf(0.5f, tanhfast(gv[4]), 0.5f);
      float fg = fmaf(0.5f, tanhfast(gv[5]), 0.5f);
      float zg = tanhfast(gv[6]);
      float og = fmaf(0.5f, tanhfast(gv[7]), 0.5f);
      c1 = fg*c1 + ig*zg; hl1 = og*tanhfast(c1);
    }
    {
      float ig = fmaf(0.5f, tanhfast(gv[8]), 0.5f);
      float fg = fmaf(0.5f, tanhfast(gv[9]), 0.5f);
      float zg = tanhfast(gv[10]);
      float og = fmaf(0.5f, tanhfast(gv[11]), 0.5f);
      c2 = fg*c2 + ig*zg; hl2 = og*tanhfast(c2);
    }

    // ---- publish ----
    if (l < LL-1){
      if (t >= RING && last_out + RING < t+1){
        do { last_out = ld_acq(flag_out); } while (last_out + RING < t+1);
      }
      float* dst = ringo + (size_t)(t & RM)*BH + b*12 + 3*q;
      __stcg(dst,     hl0);
      __stcg(dst + 1, hl1);
      __stcg(dst + 2, hl2);
    }
    __syncwarp();
    if (lane == 0) st_rel(flag_me, t+1);
  }

  int base = l*BH + b*12 + 3*q;
  g_hlast[base]     = hl0;
  g_hlast[base + 1] = hl1;
  g_hlast[base + 2] = hl2;
}

// ---------------- head: lin1/lin2 -> out, mu, softplus(sigma) ----------------
__global__ void k_head(const float* __restrict__ l1w, const float* __restrict__ l1b,
                       const float* __restrict__ l2w, const float* __restrict__ l2b,
                       const float* __restrict__ muw, const float* __restrict__ mub,
                       const float* __restrict__ sgw, const float* __restrict__ sgb,
                       float* __restrict__ out){
  int idx = blockIdx.x*blockDim.x + threadIdx.x;
  if (idx >= BB*LL) return;
  int b = idx / LL, l = idx % LL;
  const float* hv = g_hlast + l*BH + b*12;
  float h0[12], h1[12], h2[12];
  #pragma unroll
  for (int k = 0; k < 12; k++) h0[k] = hv[k];
  #pragma unroll
  for (int i = 0; i < 12; i++){
    float a = l1b[i];
    #pragma unroll
    for (int j = 0; j < 12; j++) a += l1w[i*12+j]*h0[j];
    h1[i] = fmaxf(a, 0.f);
  }
  #pragma unroll
  for (int i = 0; i < 12; i++){
    float a = l2b[i];
    #pragma unroll
    for (int j = 0; j < 12; j++) a += l2w[i*12+j]*h1[j];
    h2[i] = fmaxf(a, 0.f);
  }
  int base = (b*LL + l)*12;
  #pragma unroll
  for (int i = 0; i < 12; i++) out[base + i] = h2[i];
  #pragma unroll
  for (int i = 0; i < 12; i++){
    float a = mub[i];
    #pragma unroll
    for (int j = 0; j < 12; j++) a += muw[i*12+j]*h2[j];
    out[OUTSZ + base + i] = a;
  }
  #pragma unroll
  for (int i = 0; i < 12; i++){
    float a = sgb[i];
    #pragma unroll
    for (int j = 0; j < 12; j++) a += sgw[i*12+j]*h2[j];
    out[2*OUTSZ + base + i] = fmaxf(a, 0.f) + log1pf(__expf(-fabsf(a)));
  }
}

extern "C" void kernel_launch(void* const* d_in, const int* in_sizes, int n_in,
                              void* d_out, int out_size) {
  const float* x     = (const float*)d_in[0];
  const float* c1w   = (const float*)d_in[1];
  const float* c1b   = (const float*)d_in[2];
  const float* bn1g  = (const float*)d_in[3];
  const float* bn1b  = (const float*)d_in[4];
  const float* c2w   = (const float*)d_in[5];
  const float* c2b   = (const float*)d_in[6];
  const float* bn2g  = (const float*)d_in[7];
  const float* bn2b  = (const float*)d_in[8];
  const float* aw    = (const float*)d_in[9];
  const float* ab    = (const float*)d_in[10];
  const float* wih   = (const float*)d_in[11];
  const float* whh   = (const float*)d_in[12];
  const float* bih   = (const float*)d_in[13];
  const float* bhh   = (const float*)d_in[14];
  const float* l1w   = (const float*)d_in[15];
  const float* l1b   = (const float*)d_in[16];
  const float* l2w   = (const float*)d_in[17];
  const float* l2b   = (const float*)d_in[18];
  const float* muw   = (const float*)d_in[19];
  const float* mub   = (const float*)d_in[20];
  const float* sgw   = (const float*)d_in[21];
  const float* sgb   = (const float*)d_in[22];
  float* out = (float*)d_out;

  k_conv1<<<BB, 256>>>(x, c1w, c1b);
  k_conv2<<<BB, 256>>>(c2w, c2b, bn1g, bn1b);
  k_attn<<<BB, 256>>>(bn2g, bn2b, aw, ab);
  k_lstm<<<LL, 256>>>(wih, whh, bih, bhh);
  k_head<<<(BB*LL + 127)/128, 128>>>(l1w, l1b, l2w, l2b, muw, mub, sgw, sgb, out);
}